// round 2
// baseline (speedup 1.0000x reference)
#include <cuda_runtime.h>
#include <cub/cub.cuh>
#include <cstdint>

// ---------------- problem constants ----------------
#define NPTS     3145728
#define GDIM     128
#define NUM_VOX  2097152   // GDIM^3
#define KCAP     16
#define DDESC    24

// output layout (floats), tuple order of the reference
#define OFF_PTS   ((size_t)0)
#define OFF_CONF  ((size_t)3 * NPTS)
#define OFF_DESC  ((size_t)4 * NPTS)
#define OFF_DC    ((size_t)28 * NPTS)
#define OFF_GRID  ((size_t)29 * NPTS)
#define OFF_VC    (OFF_GRID + (size_t)NUM_VOX * KCAP)

// ---------------- device scratch (static: no allocation allowed) ----------------
__device__ unsigned g_keyA[NPTS];
__device__ unsigned g_valA[NPTS];
__device__ unsigned g_keyB[NPTS];
__device__ unsigned g_valB[NPTS];
__device__ unsigned g_vid[NPTS];
__device__ unsigned g_order1[NPTS];
__device__ unsigned g_counts[NUM_VOX + 1];
__device__ unsigned g_offsets[NUM_VOX + 1];
__device__ unsigned g_cvals[NUM_VOX + 1];
__device__ unsigned g_coffs[NUM_VOX + 1];
__device__ unsigned char g_temp[(size_t)192 * 1024 * 1024];

// ---------------- kernels ----------------

// Pass 1: voxel id + histogram + descending-conf sort keys.
__global__ void k_prep(const float* __restrict__ pts,
                       const float* __restrict__ conf,
                       const float* __restrict__ center) {
    int i = blockIdx.x * blockDim.x + threadIdx.x;
    if (i >= NPTS) return;

    // constants computed exactly as the python reference does (double -> f32)
    const float HALF = (float)((256.0 * 0.02) / 2.0);   // CUBE/2
    // XLA algebraic simplifier rewrites divide-by-constant into multiply by
    // reciprocal; f32(1 / f32(0.04)) rounds to exactly 25.0f.
    const float INV_MRES = 25.0f;

    float mx = center[0] - HALF;
    float my = center[1] - HALF;
    float mz = center[2] - HALF;

    float px = pts[3 * (size_t)i + 0];
    float py = pts[3 * (size_t)i + 1];
    float pz = pts[3 * (size_t)i + 2];

    // (p - m) * 25.0f, trunc toward zero, matching XLA's lowering of
    // ((pts - min_corner) / M_RES).astype(int32)
    int ix = (int)((px - mx) * INV_MRES);
    int iy = (int)((py - my) * INV_MRES);
    int iz = (int)((pz - mz) * INV_MRES);

    bool inb = (ix >= 0) && (ix < GDIM) && (iy >= 0) && (iy < GDIM) &&
               (iz >= 0) && (iz < GDIM);
    unsigned v = inb ? (unsigned)(ix * GDIM * GDIM + iy * GDIM + iz)
                     : (unsigned)NUM_VOX;
    g_vid[i] = v;
    atomicAdd(&g_counts[v], 1u);

    // conf >= 0: ascending sort of ~bits == descending sort of value, stable.
    g_keyA[i] = ~__float_as_uint(conf[i]);
    g_valA[i] = (unsigned)i;
}

// After sort1 (keyB/valB hold conf-desc order): save order1, build sort2 input.
__global__ void k_gather() {
    int i = blockIdx.x * blockDim.x + threadIdx.x;
    if (i >= NPTS) return;
    unsigned p = g_valB[i];      // order1[i]
    g_order1[i] = p;
    g_keyA[i] = g_vid[p];        // vid1[i]
    g_valA[i] = p;               // payload = original point id
}

// capped counts for the compaction scan
__global__ void k_capped() {
    int v = blockIdx.x * blockDim.x + threadIdx.x;
    if (v > NUM_VOX) return;
    g_cvals[v] = (v < NUM_VOX) ? min(g_counts[v], (unsigned)KCAP) : 0u;
}

// grid + vox_counts written analytically (no scatter needed)
__global__ void k_grid(float* __restrict__ out) {
    int v = blockIdx.x * blockDim.x + threadIdx.x;
    if (v >= NUM_VOX) return;
    unsigned c = min(g_counts[v], (unsigned)KCAP);
    unsigned base = g_coffs[v];
    float vals[KCAP];
#pragma unroll
    for (int s = 0; s < KCAP; s++)
        vals[s] = (s < (int)c) ? (float)(base + (unsigned)s) : -1.0f;
    float4* gp = (float4*)(out + OFF_GRID + (size_t)v * KCAP);
#pragma unroll
    for (int q = 0; q < 4; q++)
        gp[q] = make_float4(vals[4 * q], vals[4 * q + 1], vals[4 * q + 2],
                            vals[4 * q + 3]);
    out[OFF_VC + v] = (float)c;
}

// main scatter of surviving points
__global__ void k_scatter(const float* __restrict__ pts,
                          const float* __restrict__ conf,
                          const float* __restrict__ desc,
                          const float* __restrict__ dconf,
                          const float* __restrict__ dmean,
                          const float* __restrict__ dstd,
                          const float* __restrict__ dcm,
                          const float* __restrict__ dcs,
                          float* __restrict__ out) {
    int i = blockIdx.x * blockDim.x + threadIdx.x;
    if (i >= NPTS) return;
    unsigned v = g_keyB[i];               // vid_s
    if (v >= NUM_VOX) return;
    unsigned pos = (unsigned)i - g_offsets[v];
    if (pos >= KCAP) return;
    unsigned o = g_coffs[v] + pos;        // compact slot (out_idx)
    unsigned p = g_valB[i];               // pid_s (original point id)

    // pts
    out[OFF_PTS + 3 * (size_t)o + 0] = pts[3 * (size_t)p + 0];
    out[OFF_PTS + 3 * (size_t)o + 1] = pts[3 * (size_t)p + 1];
    out[OFF_PTS + 3 * (size_t)o + 2] = pts[3 * (size_t)p + 2];

    // faithful reference quirk: conf_sorted indexed by original point id
    out[OFF_CONF + o] = conf[g_order1[p]];

    // desc_conf normalized (runtime divisor -> true IEEE division in XLA too)
    out[OFF_DC + o] = __fdiv_rn(dconf[p] - dcm[0], dcs[0]);

    // desc normalized (96B aligned rows -> float4 x6)
    const float4* dsrc = (const float4*)(desc + (size_t)DDESC * p);
    float4* ddst = (float4*)(out + OFF_DESC + (size_t)DDESC * o);
    const float4* m4 = (const float4*)dmean;
    const float4* s4 = (const float4*)dstd;
#pragma unroll
    for (int q = 0; q < 6; q++) {
        float4 d = dsrc[q];
        float4 m = m4[q];
        float4 s = s4[q];
        float4 r;
        r.x = __fdiv_rn(d.x - m.x, s.x);
        r.y = __fdiv_rn(d.y - m.y, s.y);
        r.z = __fdiv_rn(d.z - m.z, s.z);
        r.w = __fdiv_rn(d.w - m.w, s.w);
        ddst[q] = r;
    }
}

// zero rows [M, N) of the point-wise outputs (d_out is poisoned before timing)
__global__ void k_zero_tail(float* __restrict__ out) {
    int r = blockIdx.x * blockDim.x + threadIdx.x;
    if (r >= NPTS) return;
    unsigned M = g_coffs[NUM_VOX];   // total surviving points
    if ((unsigned)r < M) return;
    out[OFF_PTS + 3 * (size_t)r + 0] = 0.0f;
    out[OFF_PTS + 3 * (size_t)r + 1] = 0.0f;
    out[OFF_PTS + 3 * (size_t)r + 2] = 0.0f;
    out[OFF_CONF + r] = 0.0f;
    out[OFF_DC + r] = 0.0f;
    float4 z = make_float4(0.f, 0.f, 0.f, 0.f);
    float4* dz = (float4*)(out + OFF_DESC + (size_t)DDESC * r);
#pragma unroll
    for (int q = 0; q < 6; q++) dz[q] = z;
}

// ---------------- launch ----------------
extern "C" void kernel_launch(void* const* d_in, const int* in_sizes, int n_in,
                              void* d_out, int out_size) {
    const float* pts    = (const float*)d_in[0];
    const float* conf   = (const float*)d_in[1];
    const float* desc   = (const float*)d_in[2];
    const float* dconf  = (const float*)d_in[3];
    const float* dmean  = (const float*)d_in[4];
    const float* dstd   = (const float*)d_in[5];
    const float* dcm    = (const float*)d_in[6];
    const float* dcs    = (const float*)d_in[7];
    const float* center = (const float*)d_in[8];
    float* out = (float*)d_out;

    void *pKeyA, *pValA, *pKeyB, *pValB, *pCnt, *pOff, *pCv, *pCo, *pTmp;
    cudaGetSymbolAddress(&pKeyA, g_keyA);
    cudaGetSymbolAddress(&pValA, g_valA);
    cudaGetSymbolAddress(&pKeyB, g_keyB);
    cudaGetSymbolAddress(&pValB, g_valB);
    cudaGetSymbolAddress(&pCnt,  g_counts);
    cudaGetSymbolAddress(&pOff,  g_offsets);
    cudaGetSymbolAddress(&pCv,   g_cvals);
    cudaGetSymbolAddress(&pCo,   g_coffs);
    cudaGetSymbolAddress(&pTmp,  g_temp);
    const size_t TEMP_CAP = (size_t)192 * 1024 * 1024;

    const int T = 256;
    const int GN = (NPTS + T - 1) / T;
    const int GV = (NUM_VOX + T - 1) / T;
    const int GV1 = (NUM_VOX + 1 + T - 1) / T;

    cudaMemsetAsync(pCnt, 0, (size_t)(NUM_VOX + 1) * sizeof(unsigned));

    k_prep<<<GN, T>>>(pts, conf, center);

    // sort 1: stable, 32-bit descending-conf keys -> order1 in g_valB
    size_t tb = 0;
    cub::DeviceRadixSort::SortPairs(nullptr, tb,
        (const unsigned*)pKeyA, (unsigned*)pKeyB,
        (const unsigned*)pValA, (unsigned*)pValB, NPTS, 0, 32);
    if (tb <= TEMP_CAP)
        cub::DeviceRadixSort::SortPairs(pTmp, tb,
            (const unsigned*)pKeyA, (unsigned*)pKeyB,
            (const unsigned*)pValA, (unsigned*)pValB, NPTS, 0, 32);

    k_gather<<<GN, T>>>();

    // sort 2: stable, 22-bit voxel ids (sentinel = 2^21) -> (vid_s, pid_s)
    size_t tb2 = 0;
    cub::DeviceRadixSort::SortPairs(nullptr, tb2,
        (const unsigned*)pKeyA, (unsigned*)pKeyB,
        (const unsigned*)pValA, (unsigned*)pValB, NPTS, 0, 22);
    if (tb2 <= TEMP_CAP)
        cub::DeviceRadixSort::SortPairs(pTmp, tb2,
            (const unsigned*)pKeyA, (unsigned*)pKeyB,
            (const unsigned*)pValA, (unsigned*)pValB, NPTS, 0, 22);

    // offsets = exclusive scan of counts (voxel start in sorted order)
    size_t sb = 0;
    cub::DeviceScan::ExclusiveSum(nullptr, sb,
        (const unsigned*)pCnt, (unsigned*)pOff, NUM_VOX + 1);
    if (sb <= TEMP_CAP)
        cub::DeviceScan::ExclusiveSum(pTmp, sb,
            (const unsigned*)pCnt, (unsigned*)pOff, NUM_VOX + 1);

    // capped offsets = exclusive scan of min(counts,K)  (compaction index base)
    k_capped<<<GV1, T>>>();
    size_t sb2 = 0;
    cub::DeviceScan::ExclusiveSum(nullptr, sb2,
        (const unsigned*)pCv, (unsigned*)pCo, NUM_VOX + 1);
    if (sb2 <= TEMP_CAP)
        cub::DeviceScan::ExclusiveSum(pTmp, sb2,
            (const unsigned*)pCv, (unsigned*)pCo, NUM_VOX + 1);

    k_grid<<<GV, T>>>(out);
    k_scatter<<<GN, T>>>(pts, conf, desc, dconf, dmean, dstd, dcm, dcs, out);
    k_zero_tail<<<GN, T>>>(out);
}

// round 3
// speedup vs baseline: 1.0133x; 1.0133x over previous
#include <cuda_runtime.h>
#include <cub/cub.cuh>
#include <cstdint>

// ---------------- problem constants ----------------
#define NPTS     3145728
#define GDIM     128
#define NUM_VOX  2097152   // GDIM^3
#define KCAP     16
#define DDESC    24

// output layout (floats), tuple order of the reference
#define OFF_PTS   ((size_t)0)
#define OFF_CONF  ((size_t)3 * NPTS)
#define OFF_DESC  ((size_t)4 * NPTS)
#define OFF_DC    ((size_t)28 * NPTS)
#define OFF_GRID  ((size_t)29 * NPTS)
#define OFF_VC    (OFF_GRID + (size_t)NUM_VOX * KCAP)

// ---------------- device scratch (static: no allocation allowed) ----------------
__device__ unsigned g_keyA[NPTS];
__device__ unsigned g_valA[NPTS];
__device__ unsigned g_keyB[NPTS];
__device__ unsigned g_valB[NPTS];
__device__ unsigned g_vid[NPTS];
__device__ float    g_confs[NPTS];                      // sorted conf values
__device__ unsigned g_counts[NUM_VOX + 1];
__device__ unsigned long long g_cvals64[NUM_VOX + 1];   // (capped<<32)|count
__device__ unsigned long long g_scan64[NUM_VOX + 1];    // (coffs <<32)|offsets
__device__ unsigned char g_temp[(size_t)192 * 1024 * 1024];

// ---------------- kernels ----------------

// Pass 1: voxel id + histogram + descending-conf sort keys.
__global__ void k_prep(const float* __restrict__ pts,
                       const float* __restrict__ conf,
                       const float* __restrict__ center) {
    int i = blockIdx.x * blockDim.x + threadIdx.x;
    if (i >= NPTS) return;

    const float HALF = (float)((256.0 * 0.02) / 2.0);   // CUBE/2
    // XLA rewrites divide-by-constant into multiply by reciprocal;
    // f32(1 / f32(0.04)) rounds to exactly 25.0f.
    const float INV_MRES = 25.0f;

    float mx = center[0] - HALF;
    float my = center[1] - HALF;
    float mz = center[2] - HALF;

    float px = pts[3 * (size_t)i + 0];
    float py = pts[3 * (size_t)i + 1];
    float pz = pts[3 * (size_t)i + 2];

    int ix = (int)((px - mx) * INV_MRES);
    int iy = (int)((py - my) * INV_MRES);
    int iz = (int)((pz - mz) * INV_MRES);

    bool inb = (ix >= 0) && (ix < GDIM) && (iy >= 0) && (iy < GDIM) &&
               (iz >= 0) && (iz < GDIM);
    unsigned v = inb ? (unsigned)(ix * GDIM * GDIM + iy * GDIM + iz)
                     : (unsigned)NUM_VOX;
    g_vid[i] = v;
    atomicAdd(&g_counts[v], 1u);

    // conf >= 0: ascending sort of ~bits == descending sort of value, stable.
    g_keyA[i] = ~__float_as_uint(conf[i]);
    g_valA[i] = (unsigned)i;
}

// After sort1 (keyB/valB = conf-desc order): build sort2 input + conf_sorted.
__global__ void k_gather() {
    int i = blockIdx.x * blockDim.x + threadIdx.x;
    if (i >= NPTS) return;
    unsigned p = g_valB[i];                       // order1[i]
    g_confs[i] = __uint_as_float(~g_keyB[i]);     // conf_sorted[i], sequential
    g_keyA[i] = g_vid[p];                         // vid1[i]  (L2-resident gather)
    g_valA[i] = p;                                // payload = original point id
}

// packed counts for the fused dual scan
__global__ void k_capped() {
    int v = blockIdx.x * blockDim.x + threadIdx.x;
    if (v > NUM_VOX) return;
    unsigned c = g_counts[v];
    unsigned capped = (v < NUM_VOX) ? min(c, (unsigned)KCAP) : 0u;
    g_cvals64[v] = ((unsigned long long)capped << 32) | (unsigned long long)c;
}

// grid + vox_counts written analytically (no scatter needed)
__global__ void k_grid(float* __restrict__ out) {
    int v = blockIdx.x * blockDim.x + threadIdx.x;
    if (v >= NUM_VOX) return;
    unsigned c = (unsigned)(g_cvals64[v] >> 32);          // min(count,16)
    unsigned base = (unsigned)(g_scan64[v] >> 32);        // coffs[v]
    float vals[KCAP];
#pragma unroll
    for (int s = 0; s < KCAP; s++)
        vals[s] = (s < (int)c) ? (float)(base + (unsigned)s) : -1.0f;
    float4* gp = (float4*)(out + OFF_GRID + (size_t)v * KCAP);
#pragma unroll
    for (int q = 0; q < 4; q++)
        gp[q] = make_float4(vals[4 * q], vals[4 * q + 1], vals[4 * q + 2],
                            vals[4 * q + 3]);
    out[OFF_VC + v] = (float)c;
}

// main scatter of surviving points
__global__ void k_scatter(const float* __restrict__ pts,
                          const float* __restrict__ desc,
                          const float* __restrict__ dconf,
                          const float* __restrict__ dmean,
                          const float* __restrict__ dstd,
                          const float* __restrict__ dcm,
                          const float* __restrict__ dcs,
                          float* __restrict__ out) {
    int i = blockIdx.x * blockDim.x + threadIdx.x;
    if (i >= NPTS) return;
    unsigned v = g_keyB[i];               // vid_s
    if (v >= NUM_VOX) return;
    unsigned long long s = g_scan64[v];   // one word: offsets | coffs
    unsigned pos = (unsigned)i - (unsigned)s;
    if (pos >= KCAP) return;
    unsigned o = (unsigned)(s >> 32) + pos;  // compact slot (out_idx)
    unsigned p = g_valB[i];                  // pid_s (original point id)

    // pts
    out[OFF_PTS + 3 * (size_t)o + 0] = pts[3 * (size_t)p + 0];
    out[OFF_PTS + 3 * (size_t)o + 1] = pts[3 * (size_t)p + 1];
    out[OFF_PTS + 3 * (size_t)o + 2] = pts[3 * (size_t)p + 2];

    // faithful reference quirk: conf_sorted indexed by original point id
    out[OFF_CONF + o] = g_confs[p];

    // desc_conf normalized (runtime divisor -> true IEEE division in XLA too)
    out[OFF_DC + o] = __fdiv_rn(dconf[p] - dcm[0], dcs[0]);

    // desc normalized (96B aligned rows -> float4 x6)
    const float4* dsrc = (const float4*)(desc + (size_t)DDESC * p);
    float4* ddst = (float4*)(out + OFF_DESC + (size_t)DDESC * o);
    const float4* m4 = (const float4*)dmean;
    const float4* s4 = (const float4*)dstd;
#pragma unroll
    for (int q = 0; q < 6; q++) {
        float4 d = dsrc[q];
        float4 m = m4[q];
        float4 s2 = s4[q];
        float4 r;
        r.x = __fdiv_rn(d.x - m.x, s2.x);
        r.y = __fdiv_rn(d.y - m.y, s2.y);
        r.z = __fdiv_rn(d.z - m.z, s2.z);
        r.w = __fdiv_rn(d.w - m.w, s2.w);
        ddst[q] = r;
    }
}

// zero rows [M, N) of the point-wise outputs (d_out is poisoned before timing)
__global__ void k_zero_tail(float* __restrict__ out) {
    int r = blockIdx.x * blockDim.x + threadIdx.x;
    if (r >= NPTS) return;
    unsigned M = (unsigned)(g_scan64[NUM_VOX] >> 32);  // total surviving points
    if ((unsigned)r < M) return;
    out[OFF_PTS + 3 * (size_t)r + 0] = 0.0f;
    out[OFF_PTS + 3 * (size_t)r + 1] = 0.0f;
    out[OFF_PTS + 3 * (size_t)r + 2] = 0.0f;
    out[OFF_CONF + r] = 0.0f;
    out[OFF_DC + r] = 0.0f;
    float4 z = make_float4(0.f, 0.f, 0.f, 0.f);
    float4* dz = (float4*)(out + OFF_DESC + (size_t)DDESC * r);
#pragma unroll
    for (int q = 0; q < 6; q++) dz[q] = z;
}

// ---------------- launch ----------------
extern "C" void kernel_launch(void* const* d_in, const int* in_sizes, int n_in,
                              void* d_out, int out_size) {
    const float* pts    = (const float*)d_in[0];
    const float* conf   = (const float*)d_in[1];
    const float* desc   = (const float*)d_in[2];
    const float* dconf  = (const float*)d_in[3];
    const float* dmean  = (const float*)d_in[4];
    const float* dstd   = (const float*)d_in[5];
    const float* dcm    = (const float*)d_in[6];
    const float* dcs    = (const float*)d_in[7];
    const float* center = (const float*)d_in[8];
    float* out = (float*)d_out;

    void *pKeyA, *pValA, *pKeyB, *pValB, *pCnt, *pCv, *pCo, *pTmp;
    cudaGetSymbolAddress(&pKeyA, g_keyA);
    cudaGetSymbolAddress(&pValA, g_valA);
    cudaGetSymbolAddress(&pKeyB, g_keyB);
    cudaGetSymbolAddress(&pValB, g_valB);
    cudaGetSymbolAddress(&pCnt,  g_counts);
    cudaGetSymbolAddress(&pCv,   g_cvals64);
    cudaGetSymbolAddress(&pCo,   g_scan64);
    cudaGetSymbolAddress(&pTmp,  g_temp);
    const size_t TEMP_CAP = (size_t)192 * 1024 * 1024;

    const int T = 256;
    const int GN = (NPTS + T - 1) / T;
    const int GV = (NUM_VOX + T - 1) / T;
    const int GV1 = (NUM_VOX + 1 + T - 1) / T;

    cudaMemsetAsync(pCnt, 0, (size_t)(NUM_VOX + 1) * sizeof(unsigned));

    k_prep<<<GN, T>>>(pts, conf, center);

    // sort 1: stable, 32-bit descending-conf keys -> order1 in g_valB
    size_t tb = 0;
    cub::DeviceRadixSort::SortPairs(nullptr, tb,
        (const unsigned*)pKeyA, (unsigned*)pKeyB,
        (const unsigned*)pValA, (unsigned*)pValB, NPTS, 0, 32);
    if (tb <= TEMP_CAP)
        cub::DeviceRadixSort::SortPairs(pTmp, tb,
            (const unsigned*)pKeyA, (unsigned*)pKeyB,
            (const unsigned*)pValA, (unsigned*)pValB, NPTS, 0, 32);

    k_gather<<<GN, T>>>();

    // sort 2: stable, 22-bit voxel ids (sentinel = 2^21) -> (vid_s, pid_s)
    size_t tb2 = 0;
    cub::DeviceRadixSort::SortPairs(nullptr, tb2,
        (const unsigned*)pKeyA, (unsigned*)pKeyB,
        (const unsigned*)pValA, (unsigned*)pValB, NPTS, 0, 22);
    if (tb2 <= TEMP_CAP)
        cub::DeviceRadixSort::SortPairs(pTmp, tb2,
            (const unsigned*)pKeyA, (unsigned*)pKeyB,
            (const unsigned*)pValA, (unsigned*)pValB, NPTS, 0, 22);

    // fused dual exclusive scan: low32 = offsets (scan of counts),
    // high32 = coffs (scan of min(counts,16)); no cross-field carry possible.
    k_capped<<<GV1, T>>>();
    size_t sb = 0;
    cub::DeviceScan::ExclusiveSum(nullptr, sb,
        (const unsigned long long*)pCv, (unsigned long long*)pCo, NUM_VOX + 1);
    if (sb <= TEMP_CAP)
        cub::DeviceScan::ExclusiveSum(pTmp, sb,
            (const unsigned long long*)pCv, (unsigned long long*)pCo,
            NUM_VOX + 1);

    k_grid<<<GV, T>>>(out);
    k_scatter<<<GN, T>>>(pts, desc, dconf, dmean, dstd, dcm, dcs, out);
    k_zero_tail<<<GN, T>>>(out);
}

// round 4
// speedup vs baseline: 1.0460x; 1.0322x over previous
#include <cuda_runtime.h>
#include <cub/cub.cuh>
#include <cstdint>

// ---------------- problem constants ----------------
#define NPTS     3145728
#define GDIM     128
#define NUM_VOX  2097152   // GDIM^3
#define KCAP     16
#define DDESC    24

// output layout (floats), tuple order of the reference
#define OFF_PTS   ((size_t)0)
#define OFF_CONF  ((size_t)3 * NPTS)
#define OFF_DESC  ((size_t)4 * NPTS)
#define OFF_DC    ((size_t)28 * NPTS)
#define OFF_GRID  ((size_t)29 * NPTS)
#define OFF_VC    (OFF_GRID + (size_t)NUM_VOX * KCAP)

// ---------------- device scratch (static: no allocation allowed) ----------------
__device__ unsigned g_vid[NPTS];
__device__ unsigned g_sconf[NPTS];                    // conf bits, ascending-sorted
__device__ unsigned g_pid[NPTS];                      // compact slot -> point id
__device__ unsigned long long g_bins[NPTS];           // per-voxel (~conf,idx) keys
__device__ unsigned g_counts[NUM_VOX + 1];
__device__ unsigned g_cursor[NUM_VOX];
__device__ unsigned long long g_cvals64[NUM_VOX + 1]; // (capped<<32)|count
__device__ unsigned long long g_scan64[NUM_VOX + 1];  // (coffs <<32)|offsets
__device__ unsigned char g_temp[(size_t)64 * 1024 * 1024];

// ---------------- kernels ----------------

// voxel id + histogram
__global__ void k_prep(const float* __restrict__ pts,
                       const float* __restrict__ center) {
    int i = blockIdx.x * blockDim.x + threadIdx.x;
    if (i >= NPTS) return;

    const float HALF = (float)((256.0 * 0.02) / 2.0);   // CUBE/2
    // XLA rewrites divide-by-constant into multiply by reciprocal;
    // f32(1 / f32(0.04)) rounds to exactly 25.0f.
    const float INV_MRES = 25.0f;

    float mx = center[0] - HALF;
    float my = center[1] - HALF;
    float mz = center[2] - HALF;

    float px = pts[3 * (size_t)i + 0];
    float py = pts[3 * (size_t)i + 1];
    float pz = pts[3 * (size_t)i + 2];

    int ix = (int)((px - mx) * INV_MRES);
    int iy = (int)((py - my) * INV_MRES);
    int iz = (int)((pz - mz) * INV_MRES);

    bool inb = (ix >= 0) && (ix < GDIM) && (iy >= 0) && (iy < GDIM) &&
               (iz >= 0) && (iz < GDIM);
    unsigned v = inb ? (unsigned)(ix * GDIM * GDIM + iy * GDIM + iz)
                     : (unsigned)NUM_VOX;
    g_vid[i] = v;
    atomicAdd(&g_counts[v], 1u);
}

// packed counts for the fused dual scan
__global__ void k_capped() {
    int v = blockIdx.x * blockDim.x + threadIdx.x;
    if (v > NUM_VOX) return;
    unsigned c = g_counts[v];
    unsigned capped = (v < NUM_VOX) ? min(c, (unsigned)KCAP) : 0u;
    g_cvals64[v] = ((unsigned long long)capped << 32) | (unsigned long long)c;
}

// counting-sort binning: key encodes (conf desc, idx asc); arrival order
// within a voxel is arbitrary (atomics) but the per-voxel sort in k_rank
// makes the final result deterministic.
__global__ void k_bin(const float* __restrict__ conf) {
    int i = blockIdx.x * blockDim.x + threadIdx.x;
    if (i >= NPTS) return;
    unsigned v = g_vid[i];
    if (v >= NUM_VOX) return;
    unsigned off = (unsigned)g_scan64[v];           // offsets[v]
    unsigned slot = atomicAdd(&g_cursor[v], 1u);
    unsigned long long key =
        ((unsigned long long)(~__float_as_uint(conf[i])) << 32) |
        (unsigned long long)(unsigned)i;
    g_bins[off + slot] = key;
}

// per-voxel top-16 selection + analytic grid/vox_counts + compact pid list
__global__ void k_rank_grid(float* __restrict__ out) {
    int v = blockIdx.x * blockDim.x + threadIdx.x;
    if (v >= NUM_VOX) return;
    unsigned long long s0 = g_scan64[v];
    unsigned long long s1 = g_scan64[v + 1];
    unsigned off  = (unsigned)s0;
    unsigned cnt  = (unsigned)s1 - off;
    unsigned base = (unsigned)(s0 >> 32);           // coffs[v]
    unsigned c = min(cnt, (unsigned)KCAP);

    // grid row + count (written for every voxel)
    float vals[KCAP];
#pragma unroll
    for (int s = 0; s < KCAP; s++)
        vals[s] = (s < (int)c) ? (float)(base + (unsigned)s) : -1.0f;
    float4* gp = (float4*)(out + OFF_GRID + (size_t)v * KCAP);
#pragma unroll
    for (int q = 0; q < 4; q++)
        gp[q] = make_float4(vals[4 * q], vals[4 * q + 1], vals[4 * q + 2],
                            vals[4 * q + 3]);
    out[OFF_VC + v] = (float)c;

    if (c == 0) return;

    // register-resident ascending top-16 (keys unique -> total order)
    unsigned long long best[KCAP];
#pragma unroll
    for (int s = 0; s < KCAP; s++) best[s] = ~0ull;
    for (unsigned j = 0; j < cnt; j++) {
        unsigned long long cur = g_bins[off + j];
        if (cur < best[KCAP - 1]) {
#pragma unroll
            for (int t = 0; t < KCAP; t++) {
                unsigned long long lo = min(best[t], cur);
                cur = max(best[t], cur);
                best[t] = lo;
            }
        }
    }
    for (unsigned s = 0; s < c; s++)
        g_pid[base + s] = (unsigned)best[s];        // low 32 = original idx
}

// output-driven gather: coalesced writes, random reads; zeros the tail.
__global__ void k_out(const float* __restrict__ pts,
                      const float* __restrict__ desc,
                      const float* __restrict__ dconf,
                      const float* __restrict__ dmean,
                      const float* __restrict__ dstd,
                      const float* __restrict__ dcm,
                      const float* __restrict__ dcs,
                      float* __restrict__ out) {
    int r = blockIdx.x * blockDim.x + threadIdx.x;
    if (r >= NPTS) return;
    unsigned M = (unsigned)(g_scan64[NUM_VOX] >> 32);   // total survivors

    if ((unsigned)r < M) {
        unsigned p = g_pid[r];

        out[OFF_PTS + 3 * (size_t)r + 0] = pts[3 * (size_t)p + 0];
        out[OFF_PTS + 3 * (size_t)r + 1] = pts[3 * (size_t)p + 1];
        out[OFF_PTS + 3 * (size_t)r + 2] = pts[3 * (size_t)p + 2];

        // faithful quirk: conf_sorted (desc) indexed by original point id.
        // desc-sorted[j] == asc-sorted[N-1-j]; only values matter (ties equal).
        out[OFF_CONF + r] = __uint_as_float(g_sconf[NPTS - 1 - p]);

        out[OFF_DC + r] = __fdiv_rn(dconf[p] - dcm[0], dcs[0]);

        const float4* dsrc = (const float4*)(desc + (size_t)DDESC * p);
        float4* ddst = (float4*)(out + OFF_DESC + (size_t)DDESC * r);
        const float4* m4 = (const float4*)dmean;
        const float4* s4 = (const float4*)dstd;
#pragma unroll
        for (int q = 0; q < 6; q++) {
            float4 d = dsrc[q];
            float4 m = m4[q];
            float4 s2 = s4[q];
            float4 w;
            w.x = __fdiv_rn(d.x - m.x, s2.x);
            w.y = __fdiv_rn(d.y - m.y, s2.y);
            w.z = __fdiv_rn(d.z - m.z, s2.z);
            w.w = __fdiv_rn(d.w - m.w, s2.w);
            ddst[q] = w;
        }
    } else {
        out[OFF_PTS + 3 * (size_t)r + 0] = 0.0f;
        out[OFF_PTS + 3 * (size_t)r + 1] = 0.0f;
        out[OFF_PTS + 3 * (size_t)r + 2] = 0.0f;
        out[OFF_CONF + r] = 0.0f;
        out[OFF_DC + r] = 0.0f;
        float4 z = make_float4(0.f, 0.f, 0.f, 0.f);
        float4* dz = (float4*)(out + OFF_DESC + (size_t)DDESC * r);
#pragma unroll
        for (int q = 0; q < 6; q++) dz[q] = z;
    }
}

// ---------------- launch ----------------
extern "C" void kernel_launch(void* const* d_in, const int* in_sizes, int n_in,
                              void* d_out, int out_size) {
    const float* pts    = (const float*)d_in[0];
    const float* conf   = (const float*)d_in[1];
    const float* desc   = (const float*)d_in[2];
    const float* dconf  = (const float*)d_in[3];
    const float* dmean  = (const float*)d_in[4];
    const float* dstd   = (const float*)d_in[5];
    const float* dcm    = (const float*)d_in[6];
    const float* dcs    = (const float*)d_in[7];
    const float* center = (const float*)d_in[8];
    float* out = (float*)d_out;

    void *pSconf, *pCnt, *pCur, *pCv, *pCo, *pTmp;
    cudaGetSymbolAddress(&pSconf, g_sconf);
    cudaGetSymbolAddress(&pCnt,   g_counts);
    cudaGetSymbolAddress(&pCur,   g_cursor);
    cudaGetSymbolAddress(&pCv,    g_cvals64);
    cudaGetSymbolAddress(&pCo,    g_scan64);
    cudaGetSymbolAddress(&pTmp,   g_temp);
    const size_t TEMP_CAP = (size_t)64 * 1024 * 1024;

    const int T = 256;
    const int GN = (NPTS + T - 1) / T;
    const int GV = (NUM_VOX + T - 1) / T;
    const int GV1 = (NUM_VOX + 1 + T - 1) / T;

    cudaMemsetAsync(pCnt, 0, (size_t)(NUM_VOX + 1) * sizeof(unsigned));
    cudaMemsetAsync(pCur, 0, (size_t)NUM_VOX * sizeof(unsigned));

    k_prep<<<GN, T>>>(pts, center);

    // keys-only sort of conf bit patterns (conf >= 0 -> bits order = value order)
    size_t tb = 0;
    cub::DeviceRadixSort::SortKeys(nullptr, tb,
        (const unsigned*)conf, (unsigned*)pSconf, NPTS, 0, 32);
    if (tb <= TEMP_CAP)
        cub::DeviceRadixSort::SortKeys(pTmp, tb,
            (const unsigned*)conf, (unsigned*)pSconf, NPTS, 0, 32);

    // fused dual exclusive scan: low32 = offsets, high32 = coffs
    k_capped<<<GV1, T>>>();
    size_t sb = 0;
    cub::DeviceScan::ExclusiveSum(nullptr, sb,
        (const unsigned long long*)pCv, (unsigned long long*)pCo, NUM_VOX + 1);
    if (sb <= TEMP_CAP)
        cub::DeviceScan::ExclusiveSum(pTmp, sb,
            (const unsigned long long*)pCv, (unsigned long long*)pCo,
            NUM_VOX + 1);

    k_bin<<<GN, T>>>(conf);
    k_rank_grid<<<GV, T>>>(out);
    k_out<<<GN, T>>>(pts, desc, dconf, dmean, dstd, dcm, dcs, out);
}